// round 6
// baseline (speedup 1.0000x reference)
#include <cuda_runtime.h>
#include <cuda_bf16.h>
#include <math.h>

#define N_NODES 100000
#define N_CLASS 10
#define HIDDEN 128
#define BN_EPS 1e-5

// ---------------- scratch (device globals; no runtime allocation) ----------------
__device__ float  g_buf1[(size_t)N_NODES * HIDDEN];   // z1 / z3
__device__ float  g_buf2[(size_t)N_NODES * HIDDEN];   // z2 / z4
__device__ float  g_agg2[(size_t)N_NODES * HIDDEN];   // layer-2 aggregation
__device__ float  g_agg1[(size_t)N_NODES * N_CLASS];  // layer-1 aggregation
__device__ double g_bnsum[4 * HIDDEN];
__device__ double g_bnsq[4 * HIDDEN];
__device__ float  g_scale[4 * HIDDEN];
__device__ float  g_shift[4 * HIDDEN];

// ---------------- vector reduction helpers (sm_90+ vector red) ----------------
__device__ __forceinline__ void red_add_v4(float* addr, float4 v) {
    asm volatile("red.global.add.v4.f32 [%0], {%1,%2,%3,%4};"
                 :: "l"(addr), "f"(v.x), "f"(v.y), "f"(v.z), "f"(v.w) : "memory");
}
__device__ __forceinline__ void red_add_v2(float* addr, float2 v) {
    asm volatile("red.global.add.v2.f32 [%0], {%1,%2};"
                 :: "l"(addr), "f"(v.x), "f"(v.y) : "memory");
}

// ---------------- layer-1 scatter: agg1[dst] += x[src], D=10 ----------------
__global__ void scatter1_kernel(const float* __restrict__ x,
                                const int* __restrict__ src,
                                const int* __restrict__ dst,
                                float* __restrict__ agg1, int E) {
    int e = blockIdx.x * blockDim.x + threadIdx.x;
    if (e >= E) return;
    int s = __ldg(&src[e]), d = __ldg(&dst[e]);
    const float2* xr = (const float2*)(x + (size_t)s * N_CLASS);   // 40B rows, 8B aligned
    float* ar = agg1 + (size_t)d * N_CLASS;
#pragma unroll
    for (int i = 0; i < 5; i++) {
        float2 v = __ldg(&xr[i]);
        red_add_v2(ar + 2 * i, v);
    }
}

// ---------------- GEMM1: z1 = (x + agg1) @ w11 + b11, K=10; accumulate BN stats ----------------
__global__ void gemm1_kernel(const float* __restrict__ x,
                             const float* __restrict__ agg1,
                             const float* __restrict__ w11,
                             const float* __restrict__ b11,
                             float* __restrict__ z1,
                             double* __restrict__ sumOut,
                             double* __restrict__ sqOut, int N) {
    __shared__ float ws[N_CLASS * HIDDEN];
    __shared__ float xs[8][N_CLASS];
    __shared__ float ssum[HIDDEN], ssq[HIDDEN];
    int tx = threadIdx.x, ty = threadIdx.y;
    int tid = ty * HIDDEN + tx;
    for (int i = tid; i < N_CLASS * HIDDEN; i += HIDDEN * 8) ws[i] = w11[i];
    if (tid < HIDDEN) { ssum[tid] = 0.f; ssq[tid] = 0.f; }
    int row = blockIdx.x * 8 + ty;
    if (tx < N_CLASS && row < N)
        xs[ty][tx] = x[(size_t)row * N_CLASS + tx] + agg1[(size_t)row * N_CLASS + tx];
    __syncthreads();
    if (row < N) {
        float z = __ldg(&b11[tx]);
#pragma unroll
        for (int k = 0; k < N_CLASS; k++) z += xs[ty][k] * ws[k * HIDDEN + tx];
        z1[(size_t)row * HIDDEN + tx] = z;
        atomicAdd(&ssum[tx], z);
        atomicAdd(&ssq[tx], z * z);
    }
    __syncthreads();
    if (tid < HIDDEN) {
        atomicAdd(&sumOut[tid], (double)ssum[tid]);
        atomicAdd(&sqOut[tid], (double)ssq[tid]);
    }
}

// ---------------- BN finalize: scale/shift per column ----------------
__global__ void bn_finalize(const double* __restrict__ sum,
                            const double* __restrict__ sq,
                            const float* __restrict__ g,
                            const float* __restrict__ t,
                            float* __restrict__ scale,
                            float* __restrict__ shift, double invN) {
    int j = threadIdx.x;
    double m = sum[j] * invN;
    double v = sq[j] * invN - m * m;
    if (v < 0.0) v = 0.0;
    double inv = (double)g[j] / sqrt(v + (double)BN_EPS);
    scale[j] = (float)inv;
    shift[j] = (float)((double)t[j] - m * inv);
}

// ---------------- main SGEMM: Zout = act(A) @ W + bias, 128x128 tile, BN-stat epilogue ----------
// MODE 0: act(z) = relu(scale*z + shift)
// MODE 1: act(z) = relu(scale*z + shift) + agg[row]
#define MTILE 128
#define APAD 129
template <int MODE>
__global__ __launch_bounds__(256) void gemmB(
    const float* __restrict__ Ain, const float* __restrict__ agg,
    const float* __restrict__ W, const float* __restrict__ bias,
    const float* __restrict__ scale, const float* __restrict__ shift,
    float* __restrict__ Zout, double* __restrict__ sumOut,
    double* __restrict__ sqOut, int N) {
    extern __shared__ float smem[];
    float* As = smem;                      // [128][129]
    float* Bs = smem + MTILE * APAD;       // [128][128]
    float* ssum = Bs + HIDDEN * HIDDEN;    // [128]
    float* ssq = ssum + HIDDEN;            // [128]
    __shared__ float sc[HIDDEN], sh[HIDDEN];

    int tid = threadIdx.x;
    int row0 = blockIdx.x * MTILE;
    if (tid < HIDDEN) {
        ssum[tid] = 0.f; ssq[tid] = 0.f;
        sc[tid] = scale[tid]; sh[tid] = shift[tid];
    }
    // load B tile (whole 128x128 weight)
    for (int i = tid; i < HIDDEN * (HIDDEN / 4); i += 256) {
        int k = i / (HIDDEN / 4), c4 = (i % (HIDDEN / 4)) * 4;
        *(float4*)&Bs[k * HIDDEN + c4] = *(const float4*)&W[k * HIDDEN + c4];
    }
    __syncthreads();
    // load + transform A tile
    for (int i = tid; i < MTILE * (HIDDEN / 4); i += 256) {
        int r = i / (HIDDEN / 4), k4 = (i % (HIDDEN / 4)) * 4;
        int gr = row0 + r;
        float4 v = make_float4(0.f, 0.f, 0.f, 0.f);
        if (gr < N) {
            float4 z = *(const float4*)&Ain[(size_t)gr * HIDDEN + k4];
            v.x = fmaxf(0.f, sc[k4 + 0] * z.x + sh[k4 + 0]);
            v.y = fmaxf(0.f, sc[k4 + 1] * z.y + sh[k4 + 1]);
            v.z = fmaxf(0.f, sc[k4 + 2] * z.z + sh[k4 + 2]);
            v.w = fmaxf(0.f, sc[k4 + 3] * z.w + sh[k4 + 3]);
            if (MODE == 1) {
                float4 a = *(const float4*)&agg[(size_t)gr * HIDDEN + k4];
                v.x += a.x; v.y += a.y; v.z += a.z; v.w += a.w;
            }
        }
        As[r * APAD + k4 + 0] = v.x;
        As[r * APAD + k4 + 1] = v.y;
        As[r * APAD + k4 + 2] = v.z;
        As[r * APAD + k4 + 3] = v.w;
    }
    __syncthreads();

    int tx = tid & 15, ty = tid >> 4;
    int c0 = tx * 8, r0 = ty * 8;
    float acc[8][8];
#pragma unroll
    for (int i = 0; i < 8; i++)
#pragma unroll
        for (int j = 0; j < 8; j++) acc[i][j] = 0.f;

#pragma unroll 4
    for (int k = 0; k < HIDDEN; k++) {
        float a[8], b[8];
#pragma unroll
        for (int i = 0; i < 8; i++) a[i] = As[(r0 + i) * APAD + k];
        float4 b0 = *(float4*)&Bs[k * HIDDEN + c0];
        float4 b1 = *(float4*)&Bs[k * HIDDEN + c0 + 4];
        b[0] = b0.x; b[1] = b0.y; b[2] = b0.z; b[3] = b0.w;
        b[4] = b1.x; b[5] = b1.y; b[6] = b1.z; b[7] = b1.w;
#pragma unroll
        for (int i = 0; i < 8; i++)
#pragma unroll
            for (int j = 0; j < 8; j++) acc[i][j] = fmaf(a[i], b[j], acc[i][j]);
    }

    // epilogue: bias, store, column stats
    float bv[8];
#pragma unroll
    for (int j = 0; j < 8; j++) bv[j] = __ldg(&bias[c0 + j]);
    float psum[8], psq[8];
#pragma unroll
    for (int j = 0; j < 8; j++) { psum[j] = 0.f; psq[j] = 0.f; }
#pragma unroll
    for (int i = 0; i < 8; i++) {
        int gr = row0 + r0 + i;
        if (gr < N) {
            float z[8];
#pragma unroll
            for (int j = 0; j < 8; j++) {
                z[j] = acc[i][j] + bv[j];
                psum[j] += z[j];
                psq[j] += z[j] * z[j];
            }
            float4 o0 = make_float4(z[0], z[1], z[2], z[3]);
            float4 o1 = make_float4(z[4], z[5], z[6], z[7]);
            *(float4*)&Zout[(size_t)gr * HIDDEN + c0] = o0;
            *(float4*)&Zout[(size_t)gr * HIDDEN + c0 + 4] = o1;
        }
    }
#pragma unroll
    for (int j = 0; j < 8; j++) {
        atomicAdd(&ssum[c0 + j], psum[j]);
        atomicAdd(&ssq[c0 + j], psq[j]);
    }
    __syncthreads();
    if (tid < HIDDEN) {
        atomicAdd(&sumOut[tid], (double)ssum[tid]);
        atomicAdd(&sqOut[tid], (double)ssq[tid]);
    }
}

// ---------------- layer-2 scatter: agg2[dst] += relu(bn(z2))[src], warp/edge, D=128 ----------
__global__ void scatter2_kernel(const float* __restrict__ z2,
                                const float* __restrict__ scale,
                                const float* __restrict__ shift,
                                const int* __restrict__ src,
                                const int* __restrict__ dst,
                                float* __restrict__ agg2, int E) {
    __shared__ float sc[HIDDEN], sh[HIDDEN];
    int tid = threadIdx.x;
    if (tid < HIDDEN) { sc[tid] = scale[tid]; sh[tid] = shift[tid]; }
    __syncthreads();
    int warp = tid >> 5, lane = tid & 31;
    int e = blockIdx.x * 8 + warp;
    if (e >= E) return;
    int s = __ldg(&src[e]);
    int d = __ldg(&dst[e]);
    int o = lane * 4;
    float4 z = *(const float4*)&z2[(size_t)s * HIDDEN + o];
    float4 v;
    v.x = fmaxf(0.f, sc[o + 0] * z.x + sh[o + 0]);
    v.y = fmaxf(0.f, sc[o + 1] * z.y + sh[o + 1]);
    v.z = fmaxf(0.f, sc[o + 2] * z.z + sh[o + 2]);
    v.w = fmaxf(0.f, sc[o + 3] * z.w + sh[o + 3]);
    red_add_v4(&agg2[(size_t)d * HIDDEN + o], v);
}

// ---------------- final: logits = relu(bn(z4)) @ wf + bf -> log_softmax, warp/row ----------
__global__ void final_kernel(const float* __restrict__ z4,
                             const float* __restrict__ scale,
                             const float* __restrict__ shift,
                             const float* __restrict__ wf,
                             const float* __restrict__ bf,
                             float* __restrict__ out, int N) {
    __shared__ float wfs[HIDDEN * N_CLASS];
    __shared__ float sc[HIDDEN], sh[HIDDEN];
    int tid = threadIdx.x;
    for (int i = tid; i < HIDDEN * N_CLASS; i += 256) wfs[i] = wf[i];
    if (tid < HIDDEN) { sc[tid] = scale[tid]; sh[tid] = shift[tid]; }
    __syncthreads();
    int warp = tid >> 5, lane = tid & 31;
    int n = blockIdx.x * 8 + warp;
    if (n >= N) return;
    int o = lane * 4;
    float4 z = *(const float4*)&z4[(size_t)n * HIDDEN + o];
    float y[4];
    y[0] = fmaxf(0.f, sc[o + 0] * z.x + sh[o + 0]);
    y[1] = fmaxf(0.f, sc[o + 1] * z.y + sh[o + 1]);
    y[2] = fmaxf(0.f, sc[o + 2] * z.z + sh[o + 2]);
    y[3] = fmaxf(0.f, sc[o + 3] * z.w + sh[o + 3]);
    float acc[N_CLASS];
#pragma unroll
    for (int j = 0; j < N_CLASS; j++) acc[j] = 0.f;
#pragma unroll
    for (int i = 0; i < 4; i++) {
        const float* wr = &wfs[(o + i) * N_CLASS];
#pragma unroll
        for (int j = 0; j < N_CLASS; j++) acc[j] = fmaf(y[i], wr[j], acc[j]);
    }
#pragma unroll
    for (int off = 16; off > 0; off >>= 1)
#pragma unroll
        for (int j = 0; j < N_CLASS; j++)
            acc[j] += __shfl_xor_sync(0xFFFFFFFFu, acc[j], off);
    if (lane == 0) {
        float l[N_CLASS];
        float m = -1e30f;
#pragma unroll
        for (int j = 0; j < N_CLASS; j++) {
            l[j] = acc[j] + __ldg(&bf[j]);
            m = fmaxf(m, l[j]);
        }
        float s = 0.f;
#pragma unroll
        for (int j = 0; j < N_CLASS; j++) s += __expf(l[j] - m);
        float lg = m + logf(s);
#pragma unroll
        for (int j = 0; j < N_CLASS; j++) out[(size_t)n * N_CLASS + j] = l[j] - lg;
    }
}

// ---------------- host launch ----------------
extern "C" void kernel_launch(void* const* d_in, const int* in_sizes, int n_in,
                              void* d_out, int out_size) {
    const float* x   = (const float*)d_in[0];
    const float* w11 = (const float*)d_in[2];
    const float* b11 = (const float*)d_in[3];
    const float* g11 = (const float*)d_in[4];
    const float* t11 = (const float*)d_in[5];
    const float* w12 = (const float*)d_in[6];
    const float* b12 = (const float*)d_in[7];
    const float* g12 = (const float*)d_in[8];
    const float* t12 = (const float*)d_in[9];
    const float* w21 = (const float*)d_in[10];
    const float* b21 = (const float*)d_in[11];
    const float* g21 = (const float*)d_in[12];
    const float* t21 = (const float*)d_in[13];
    const float* w22 = (const float*)d_in[14];
    const float* b22 = (const float*)d_in[15];
    const float* g22 = (const float*)d_in[16];
    const float* t22 = (const float*)d_in[17];
    const float* wf  = (const float*)d_in[18];
    const float* bf  = (const float*)d_in[19];
    const int*   ei  = (const int*)d_in[20];   // int32 on device (harness dtype set)

    int N = in_sizes[0] / N_CLASS;       // 100000
    int E = in_sizes[20] / 2;            // 1600000
    const int* src = ei;
    const int* dst = ei + E;

    float *agg1, *agg2, *buf1, *buf2, *scale, *shift;
    double *bnsum, *bnsq;
    cudaGetSymbolAddress((void**)&agg1, g_agg1);
    cudaGetSymbolAddress((void**)&agg2, g_agg2);
    cudaGetSymbolAddress((void**)&buf1, g_buf1);
    cudaGetSymbolAddress((void**)&buf2, g_buf2);
    cudaGetSymbolAddress((void**)&scale, g_scale);
    cudaGetSymbolAddress((void**)&shift, g_shift);
    cudaGetSymbolAddress((void**)&bnsum, g_bnsum);
    cudaGetSymbolAddress((void**)&bnsq, g_bnsq);

    const size_t SMEM_GEMM = (size_t)(MTILE * APAD + HIDDEN * HIDDEN + 2 * HIDDEN) * sizeof(float);
    cudaFuncSetAttribute(gemmB<0>, cudaFuncAttributeMaxDynamicSharedMemorySize, (int)SMEM_GEMM);
    cudaFuncSetAttribute(gemmB<1>, cudaFuncAttributeMaxDynamicSharedMemorySize, (int)SMEM_GEMM);

    cudaMemsetAsync(agg1, 0, (size_t)N * N_CLASS * sizeof(float), 0);
    cudaMemsetAsync(agg2, 0, (size_t)N * HIDDEN * sizeof(float), 0);
    cudaMemsetAsync(bnsum, 0, 4 * HIDDEN * sizeof(double), 0);
    cudaMemsetAsync(bnsq, 0, 4 * HIDDEN * sizeof(double), 0);

    double invN = 1.0 / (double)N;
    int gBlocks = (N + MTILE - 1) / MTILE;

    // layer 1
    scatter1_kernel<<<(E + 255) / 256, 256>>>(x, src, dst, agg1, E);
    gemm1_kernel<<<(N + 7) / 8, dim3(HIDDEN, 8)>>>(x, agg1, w11, b11, buf1,
                                                   bnsum + 0 * HIDDEN, bnsq + 0 * HIDDEN, N);
    bn_finalize<<<1, HIDDEN>>>(bnsum + 0 * HIDDEN, bnsq + 0 * HIDDEN, g11, t11,
                               scale + 0 * HIDDEN, shift + 0 * HIDDEN, invN);
    gemmB<0><<<gBlocks, 256, SMEM_GEMM>>>(buf1, nullptr, w12, b12,
                                          scale + 0 * HIDDEN, shift + 0 * HIDDEN,
                                          buf2, bnsum + 1 * HIDDEN, bnsq + 1 * HIDDEN, N);
    bn_finalize<<<1, HIDDEN>>>(bnsum + 1 * HIDDEN, bnsq + 1 * HIDDEN, g12, t12,
                               scale + 1 * HIDDEN, shift + 1 * HIDDEN, invN);

    // layer 2 (h_out1 = relu(bn1(z2)) recomputed on the fly; never materialized)
    scatter2_kernel<<<(E + 7) / 8, 256>>>(buf2, scale + 1 * HIDDEN, shift + 1 * HIDDEN,
                                          src, dst, agg2, E);
    gemmB<1><<<gBlocks, 256, SMEM_GEMM>>>(buf2, agg2, w21, b21,
                                          scale + 1 * HIDDEN, shift + 1 * HIDDEN,
                                          buf1, bnsum + 2 * HIDDEN, bnsq + 2 * HIDDEN, N);
    bn_finalize<<<1, HIDDEN>>>(bnsum + 2 * HIDDEN, bnsq + 2 * HIDDEN, g21, t21,
                               scale + 2 * HIDDEN, shift + 2 * HIDDEN, invN);
    gemmB<0><<<gBlocks, 256, SMEM_GEMM>>>(buf1, nullptr, w22, b22,
                                          scale + 2 * HIDDEN, shift + 2 * HIDDEN,
                                          buf2, bnsum + 3 * HIDDEN, bnsq + 3 * HIDDEN, N);
    bn_finalize<<<1, HIDDEN>>>(bnsum + 3 * HIDDEN, bnsq + 3 * HIDDEN, g22, t22,
                               scale + 3 * HIDDEN, shift + 3 * HIDDEN, invN);

    // readout
    final_kernel<<<(N + 7) / 8, 256>>>(buf2, scale + 3 * HIDDEN, shift + 3 * HIDDEN,
                                       wf, bf, (float*)d_out, N);
}

// round 8
// speedup vs baseline: 1.1300x; 1.1300x over previous
#include <cuda_runtime.h>
#include <cuda_bf16.h>
#include <math.h>

#define N_NODES 100000
#define N_CLASS 10
#define HIDDEN 128
#define BN_EPS 1e-5

// ---------------- scratch (device globals; no runtime allocation) ----------------
__device__ float  g_buf1[(size_t)N_NODES * HIDDEN];   // z1 / z3
__device__ float  g_buf2[(size_t)N_NODES * HIDDEN];   // z2 / z4
__device__ float  g_agg2[(size_t)N_NODES * HIDDEN];   // layer-2 aggregation
__device__ float  g_agg1[(size_t)N_NODES * N_CLASS];  // layer-1 aggregation
__device__ double g_bnsum[4 * HIDDEN];
__device__ double g_bnsq[4 * HIDDEN];
__device__ float  g_scale[4 * HIDDEN];
__device__ float  g_shift[4 * HIDDEN];

// ---------------- vector reduction helpers (sm_90+ vector red) ----------------
__device__ __forceinline__ void red_add_v4(float* addr, float4 v) {
    asm volatile("red.global.add.v4.f32 [%0], {%1,%2,%3,%4};"
                 :: "l"(addr), "f"(v.x), "f"(v.y), "f"(v.z), "f"(v.w) : "memory");
}
__device__ __forceinline__ void red_add_v2(float* addr, float2 v) {
    asm volatile("red.global.add.v2.f32 [%0], {%1,%2};"
                 :: "l"(addr), "f"(v.x), "f"(v.y) : "memory");
}

// ---------------- layer-1 scatter: agg1[dst] += x[src], D=10 ----------------
__global__ void scatter1_kernel(const float* __restrict__ x,
                                const int* __restrict__ src,
                                const int* __restrict__ dst,
                                float* __restrict__ agg1, int E) {
    int e = blockIdx.x * blockDim.x + threadIdx.x;
    if (e >= E) return;
    int s = __ldg(&src[e]), d = __ldg(&dst[e]);
    const float2* xr = (const float2*)(x + (size_t)s * N_CLASS);   // 40B rows, 8B aligned
    float* ar = agg1 + (size_t)d * N_CLASS;
#pragma unroll
    for (int i = 0; i < 5; i++) {
        float2 v = __ldg(&xr[i]);
        red_add_v2(ar + 2 * i, v);
    }
}

// ---------------- GEMM1: z1 = (x + agg1) @ w11 + b11, K=10; accumulate BN stats ----------------
__global__ void gemm1_kernel(const float* __restrict__ x,
                             const float* __restrict__ agg1,
                             const float* __restrict__ w11,
                             const float* __restrict__ b11,
                             float* __restrict__ z1,
                             double* __restrict__ sumOut,
                             double* __restrict__ sqOut, int N) {
    __shared__ float ws[N_CLASS * HIDDEN];
    __shared__ float xs[8][N_CLASS];
    __shared__ float ssum[HIDDEN], ssq[HIDDEN];
    int tx = threadIdx.x, ty = threadIdx.y;
    int tid = ty * HIDDEN + tx;
    for (int i = tid; i < N_CLASS * HIDDEN; i += HIDDEN * 8) ws[i] = w11[i];
    if (tid < HIDDEN) { ssum[tid] = 0.f; ssq[tid] = 0.f; }
    int row = blockIdx.x * 8 + ty;
    if (tx < N_CLASS && row < N)
        xs[ty][tx] = x[(size_t)row * N_CLASS + tx] + agg1[(size_t)row * N_CLASS + tx];
    __syncthreads();
    if (row < N) {
        float z = __ldg(&b11[tx]);
#pragma unroll
        for (int k = 0; k < N_CLASS; k++) z += xs[ty][k] * ws[k * HIDDEN + tx];
        z1[(size_t)row * HIDDEN + tx] = z;
        atomicAdd(&ssum[tx], z);
        atomicAdd(&ssq[tx], z * z);
    }
    __syncthreads();
    if (tid < HIDDEN) {
        atomicAdd(&sumOut[tid], (double)ssum[tid]);
        atomicAdd(&sqOut[tid], (double)ssq[tid]);
    }
}

// ---------------- BN finalize: scale/shift per column ----------------
__global__ void bn_finalize(const double* __restrict__ sum,
                            const double* __restrict__ sq,
                            const float* __restrict__ g,
                            const float* __restrict__ t,
                            float* __restrict__ scale,
                            float* __restrict__ shift, double invN) {
    int j = threadIdx.x;
    double m = sum[j] * invN;
    double v = sq[j] * invN - m * m;
    if (v < 0.0) v = 0.0;
    double inv = (double)g[j] / sqrt(v + (double)BN_EPS);
    scale[j] = (float)inv;
    shift[j] = (float)((double)t[j] - m * inv);
}

// ---------------- main SGEMM: Zout = act(A) @ W + bias, 128x128 tile, BN-stat epilogue ----------
// A streamed in two K-chunks of 64 so smem <= ~100KB -> 2 CTAs/SM (occupancy).
// MODE 0: act(z) = relu(scale*z + shift)
// MODE 1: act(z) = relu(scale*z + shift) + agg[row]
#define MTILE 128
#define KC 64
#define KPAD 65
template <int MODE>
__global__ __launch_bounds__(256, 2) void gemmB(
    const float* __restrict__ Ain, const float* __restrict__ agg,
    const float* __restrict__ W, const float* __restrict__ bias,
    const float* __restrict__ scale, const float* __restrict__ shift,
    float* __restrict__ Zout, double* __restrict__ sumOut,
    double* __restrict__ sqOut, int N) {
    extern __shared__ float smem[];
    float* Bs = smem;                       // [128][128]
    float* As = smem + HIDDEN * HIDDEN;     // [128][65] (one 64-wide K chunk)
    float* ssum = As + MTILE * KPAD;        // [128]
    float* ssq = ssum + HIDDEN;             // [128]
    __shared__ float sc[HIDDEN], sh[HIDDEN];

    int tid = threadIdx.x;
    int row0 = blockIdx.x * MTILE;
    if (tid < HIDDEN) {
        ssum[tid] = 0.f; ssq[tid] = 0.f;
        sc[tid] = scale[tid]; sh[tid] = shift[tid];
    }
    // load full B tile (128x128 weight)
    for (int i = tid; i < HIDDEN * (HIDDEN / 4); i += 256) {
        int k = i / (HIDDEN / 4), c4 = (i % (HIDDEN / 4)) * 4;
        *(float4*)&Bs[k * HIDDEN + c4] = *(const float4*)&W[k * HIDDEN + c4];
    }

    int tx = tid & 15, ty = tid >> 4;
    int c0 = tx * 8, r0 = ty * 8;
    float acc[8][8];
#pragma unroll
    for (int i = 0; i < 8; i++)
#pragma unroll
        for (int j = 0; j < 8; j++) acc[i][j] = 0.f;

    for (int kc = 0; kc < HIDDEN; kc += KC) {
        __syncthreads();   // protect As from previous chunk's readers; makes sc/sh/Bs visible on first pass
        // load + transform A chunk: 128 rows x 64 k
        for (int i = tid; i < MTILE * (KC / 4); i += 256) {
            int r = i / (KC / 4), k4 = (i % (KC / 4)) * 4;
            int gk = kc + k4;
            int gr = row0 + r;
            float4 v = make_float4(0.f, 0.f, 0.f, 0.f);
            if (gr < N) {
                float4 z = *(const float4*)&Ain[(size_t)gr * HIDDEN + gk];
                v.x = fmaxf(0.f, sc[gk + 0] * z.x + sh[gk + 0]);
                v.y = fmaxf(0.f, sc[gk + 1] * z.y + sh[gk + 1]);
                v.z = fmaxf(0.f, sc[gk + 2] * z.z + sh[gk + 2]);
                v.w = fmaxf(0.f, sc[gk + 3] * z.w + sh[gk + 3]);
                if (MODE == 1) {
                    float4 a = *(const float4*)&agg[(size_t)gr * HIDDEN + gk];
                    v.x += a.x; v.y += a.y; v.z += a.z; v.w += a.w;
                }
            }
            As[r * KPAD + k4 + 0] = v.x;
            As[r * KPAD + k4 + 1] = v.y;
            As[r * KPAD + k4 + 2] = v.z;
            As[r * KPAD + k4 + 3] = v.w;
        }
        __syncthreads();

#pragma unroll 4
        for (int kk = 0; kk < KC; kk++) {
            int k = kc + kk;
            float a[8], b[8];
#pragma unroll
            for (int i = 0; i < 8; i++) a[i] = As[(r0 + i) * KPAD + kk];
            float4 b0 = *(float4*)&Bs[k * HIDDEN + c0];
            float4 b1 = *(float4*)&Bs[k * HIDDEN + c0 + 4];
            b[0] = b0.x; b[1] = b0.y; b[2] = b0.z; b[3] = b0.w;
            b[4] = b1.x; b[5] = b1.y; b[6] = b1.z; b[7] = b1.w;
#pragma unroll
            for (int i = 0; i < 8; i++)
#pragma unroll
                for (int j = 0; j < 8; j++) acc[i][j] = fmaf(a[i], b[j], acc[i][j]);
        }
    }

    // epilogue: bias, store, column stats
    float bv[8];
#pragma unroll
    for (int j = 0; j < 8; j++) bv[j] = __ldg(&bias[c0 + j]);
    float psum[8], psq[8];
#pragma unroll
    for (int j = 0; j < 8; j++) { psum[j] = 0.f; psq[j] = 0.f; }
#pragma unroll
    for (int i = 0; i < 8; i++) {
        int gr = row0 + r0 + i;
        if (gr < N) {
            float z[8];
#pragma unroll
            for (int j = 0; j < 8; j++) {
                z[j] = acc[i][j] + bv[j];
                psum[j] += z[j];
                psq[j] += z[j] * z[j];
            }
            float4 o0 = make_float4(z[0], z[1], z[2], z[3]);
            float4 o1 = make_float4(z[4], z[5], z[6], z[7]);
            *(float4*)&Zout[(size_t)gr * HIDDEN + c0] = o0;
            *(float4*)&Zout[(size_t)gr * HIDDEN + c0 + 4] = o1;
        }
    }
#pragma unroll
    for (int j = 0; j < 8; j++) {
        atomicAdd(&ssum[c0 + j], psum[j]);
        atomicAdd(&ssq[c0 + j], psq[j]);
    }
    __syncthreads();
    if (tid < HIDDEN) {
        atomicAdd(&sumOut[tid], (double)ssum[tid]);
        atomicAdd(&sqOut[tid], (double)ssq[tid]);
    }
}

// ---------------- layer-2 scatter: agg2[dst] += relu(bn(z2))[src], warp/edge, D=128 ----------
__global__ void scatter2_kernel(const float* __restrict__ z2,
                                const float* __restrict__ scale,
                                const float* __restrict__ shift,
                                const int* __restrict__ src,
                                const int* __restrict__ dst,
                                float* __restrict__ agg2, int E) {
    __shared__ float sc[HIDDEN], sh[HIDDEN];
    int tid = threadIdx.x;
    if (tid < HIDDEN) { sc[tid] = scale[tid]; sh[tid] = shift[tid]; }
    __syncthreads();
    int warp = tid >> 5, lane = tid & 31;
    int e = blockIdx.x * 8 + warp;
    if (e >= E) return;
    int s = __ldg(&src[e]);
    int d = __ldg(&dst[e]);
    int o = lane * 4;
    float4 z = *(const float4*)&z2[(size_t)s * HIDDEN + o];
    float4 v;
    v.x = fmaxf(0.f, sc[o + 0] * z.x + sh[o + 0]);
    v.y = fmaxf(0.f, sc[o + 1] * z.y + sh[o + 1]);
    v.z = fmaxf(0.f, sc[o + 2] * z.z + sh[o + 2]);
    v.w = fmaxf(0.f, sc[o + 3] * z.w + sh[o + 3]);
    red_add_v4(&agg2[(size_t)d * HIDDEN + o], v);
}

// ---------------- final: logits = relu(bn(z4)) @ wf + bf -> log_softmax, warp/row ----------
__global__ void final_kernel(const float* __restrict__ z4,
                             const float* __restrict__ scale,
                             const float* __restrict__ shift,
                             const float* __restrict__ wf,
                             const float* __restrict__ bf,
                             float* __restrict__ out, int N) {
    __shared__ float wfs[HIDDEN * N_CLASS];
    __shared__ float sc[HIDDEN], sh[HIDDEN];
    int tid = threadIdx.x;
    for (int i = tid; i < HIDDEN * N_CLASS; i += 256) wfs[i] = wf[i];
    if (tid < HIDDEN) { sc[tid] = scale[tid]; sh[tid] = shift[tid]; }
    __syncthreads();
    int warp = tid >> 5, lane = tid & 31;
    int n = blockIdx.x * 8 + warp;
    if (n >= N) return;
    int o = lane * 4;
    float4 z = *(const float4*)&z4[(size_t)n * HIDDEN + o];
    float y[4];
    y[0] = fmaxf(0.f, sc[o + 0] * z.x + sh[o + 0]);
    y[1] = fmaxf(0.f, sc[o + 1] * z.y + sh[o + 1]);
    y[2] = fmaxf(0.f, sc[o + 2] * z.z + sh[o + 2]);
    y[3] = fmaxf(0.f, sc[o + 3] * z.w + sh[o + 3]);
    float acc[N_CLASS];
#pragma unroll
    for (int j = 0; j < N_CLASS; j++) acc[j] = 0.f;
#pragma unroll
    for (int i = 0; i < 4; i++) {
        const float* wr = &wfs[(o + i) * N_CLASS];
#pragma unroll
        for (int j = 0; j < N_CLASS; j++) acc[j] = fmaf(y[i], wr[j], acc[j]);
    }
#pragma unroll
    for (int off = 16; off > 0; off >>= 1)
#pragma unroll
        for (int j = 0; j < N_CLASS; j++)
            acc[j] += __shfl_xor_sync(0xFFFFFFFFu, acc[j], off);
    if (lane == 0) {
        float l[N_CLASS];
        float m = -1e30f;
#pragma unroll
        for (int j = 0; j < N_CLASS; j++) {
            l[j] = acc[j] + __ldg(&bf[j]);
            m = fmaxf(m, l[j]);
        }
        float s = 0.f;
#pragma unroll
        for (int j = 0; j < N_CLASS; j++) s += __expf(l[j] - m);
        float lg = m + logf(s);
#pragma unroll
        for (int j = 0; j < N_CLASS; j++) out[(size_t)n * N_CLASS + j] = l[j] - lg;
    }
}

// ---------------- host launch ----------------
extern "C" void kernel_launch(void* const* d_in, const int* in_sizes, int n_in,
                              void* d_out, int out_size) {
    const float* x   = (const float*)d_in[0];
    const float* w11 = (const float*)d_in[2];
    const float* b11 = (const float*)d_in[3];
    const float* g11 = (const float*)d_in[4];
    const float* t11 = (const float*)d_in[5];
    const float* w12 = (const float*)d_in[6];
    const float* b12 = (const float*)d_in[7];
    const float* g12 = (const float*)d_in[8];
    const float* t12 = (const float*)d_in[9];
    const float* w21 = (const float*)d_in[10];
    const float* b21 = (const float*)d_in[11];
    const float* g21 = (const float*)d_in[12];
    const float* t21 = (const float*)d_in[13];
    const float* w22 = (const float*)d_in[14];
    const float* b22 = (const float*)d_in[15];
    const float* g22 = (const float*)d_in[16];
    const float* t22 = (const float*)d_in[17];
    const float* wf  = (const float*)d_in[18];
    const float* bf  = (const float*)d_in[19];
    const int*   ei  = (const int*)d_in[20];   // int32 on device (harness dtype set)

    int N = in_sizes[0] / N_CLASS;       // 100000
    int E = in_sizes[20] / 2;            // 1600000
    const int* src = ei;
    const int* dst = ei + E;

    float *agg1, *agg2, *buf1, *buf2, *scale, *shift;
    double *bnsum, *bnsq;
    cudaGetSymbolAddress((void**)&agg1, g_agg1);
    cudaGetSymbolAddress((void**)&agg2, g_agg2);
    cudaGetSymbolAddress((void**)&buf1, g_buf1);
    cudaGetSymbolAddress((void**)&buf2, g_buf2);
    cudaGetSymbolAddress((void**)&scale, g_scale);
    cudaGetSymbolAddress((void**)&shift, g_shift);
    cudaGetSymbolAddress((void**)&bnsum, g_bnsum);
    cudaGetSymbolAddress((void**)&bnsq, g_bnsq);

    const size_t SMEM_GEMM = (size_t)(HIDDEN * HIDDEN + MTILE * KPAD + 2 * HIDDEN) * sizeof(float);
    cudaFuncSetAttribute(gemmB<0>, cudaFuncAttributeMaxDynamicSharedMemorySize, (int)SMEM_GEMM);
    cudaFuncSetAttribute(gemmB<1>, cudaFuncAttributeMaxDynamicSharedMemorySize, (int)SMEM_GEMM);

    cudaMemsetAsync(agg1, 0, (size_t)N * N_CLASS * sizeof(float), 0);
    cudaMemsetAsync(agg2, 0, (size_t)N * HIDDEN * sizeof(float), 0);
    cudaMemsetAsync(bnsum, 0, 4 * HIDDEN * sizeof(double), 0);
    cudaMemsetAsync(bnsq, 0, 4 * HIDDEN * sizeof(double), 0);

    double invN = 1.0 / (double)N;
    int gBlocks = (N + MTILE - 1) / MTILE;

    // layer 1
    scatter1_kernel<<<(E + 255) / 256, 256>>>(x, src, dst, agg1, E);
    gemm1_kernel<<<(N + 7) / 8, dim3(HIDDEN, 8)>>>(x, agg1, w11, b11, buf1,
                                                   bnsum + 0 * HIDDEN, bnsq + 0 * HIDDEN, N);
    bn_finalize<<<1, HIDDEN>>>(bnsum + 0 * HIDDEN, bnsq + 0 * HIDDEN, g11, t11,
                               scale + 0 * HIDDEN, shift + 0 * HIDDEN, invN);
    gemmB<0><<<gBlocks, 256, SMEM_GEMM>>>(buf1, nullptr, w12, b12,
                                          scale + 0 * HIDDEN, shift + 0 * HIDDEN,
                                          buf2, bnsum + 1 * HIDDEN, bnsq + 1 * HIDDEN, N);
    bn_finalize<<<1, HIDDEN>>>(bnsum + 1 * HIDDEN, bnsq + 1 * HIDDEN, g12, t12,
                               scale + 1 * HIDDEN, shift + 1 * HIDDEN, invN);

    // layer 2 (h_out1 = relu(bn1(z2)) recomputed on the fly; never materialized)
    scatter2_kernel<<<(E + 7) / 8, 256>>>(buf2, scale + 1 * HIDDEN, shift + 1 * HIDDEN,
                                          src, dst, agg2, E);
    gemmB<1><<<gBlocks, 256, SMEM_GEMM>>>(buf2, agg2, w21, b21,
                                          scale + 1 * HIDDEN, shift + 1 * HIDDEN,
                                          buf1, bnsum + 2 * HIDDEN, bnsq + 2 * HIDDEN, N);
    bn_finalize<<<1, HIDDEN>>>(bnsum + 2 * HIDDEN, bnsq + 2 * HIDDEN, g21, t21,
                               scale + 2 * HIDDEN, shift + 2 * HIDDEN, invN);
    gemmB<0><<<gBlocks, 256, SMEM_GEMM>>>(buf1, nullptr, w22, b22,
                                          scale + 2 * HIDDEN, shift + 2 * HIDDEN,
                                          buf2, bnsum + 3 * HIDDEN, bnsq + 3 * HIDDEN, N);
    bn_finalize<<<1, HIDDEN>>>(bnsum + 3 * HIDDEN, bnsq + 3 * HIDDEN, g22, t22,
                               scale + 3 * HIDDEN, shift + 3 * HIDDEN, invN);

    // readout
    final_kernel<<<(N + 7) / 8, 256>>>(buf2, scale + 3 * HIDDEN, shift + 3 * HIDDEN,
                                       wf, bf, (float*)d_out, N);
}

// round 15
// speedup vs baseline: 1.2711x; 1.1248x over previous
#include <cuda_runtime.h>
#include <cuda_bf16.h>
#include <stdint.h>
#include <math.h>

#define N_NODES 100000
#define N_CLASS 10
#define HIDDEN 128
#define BN_EPS 1e-5

// ---------------- scratch (device globals; no runtime allocation) ----------------
__device__ float  g_buf1[(size_t)N_NODES * HIDDEN];   // z1 / z3
__device__ float  g_buf2[(size_t)N_NODES * HIDDEN];   // z2 / z4
__device__ float  g_agg2[(size_t)N_NODES * HIDDEN];   // layer-2 aggregation
__device__ float  g_agg1[(size_t)N_NODES * N_CLASS];  // layer-1 aggregation
__device__ double g_bnsum[4 * HIDDEN];
__device__ double g_bnsq[4 * HIDDEN];
__device__ float  g_scale[4 * HIDDEN];
__device__ float  g_shift[4 * HIDDEN];

// ---------------- helpers ----------------
__device__ __forceinline__ void red_add_v4(float* addr, float4 v) {
    asm volatile("red.global.add.v4.f32 [%0], {%1,%2,%3,%4};"
                 :: "l"(addr), "f"(v.x), "f"(v.y), "f"(v.z), "f"(v.w) : "memory");
}
__device__ __forceinline__ void red_add_v2(float* addr, float2 v) {
    asm volatile("red.global.add.v2.f32 [%0], {%1,%2};"
                 :: "l"(addr), "f"(v.x), "f"(v.y) : "memory");
}
__device__ __forceinline__ float to_tf32(float x) {
    uint32_t u;
    asm("cvt.rna.tf32.f32 %0, %1;" : "=r"(u) : "f"(x));
    return __uint_as_float(u);
}
__device__ __forceinline__ void mma_tf32(float& d0, float& d1, float& d2, float& d3,
                                         uint32_t a0, uint32_t a1, uint32_t a2, uint32_t a3,
                                         uint32_t b0, uint32_t b1) {
    asm volatile("mma.sync.aligned.m16n8k8.row.col.f32.tf32.tf32.f32 "
                 "{%0,%1,%2,%3}, {%4,%5,%6,%7}, {%8,%9}, {%0,%1,%2,%3};"
                 : "+f"(d0), "+f"(d1), "+f"(d2), "+f"(d3)
                 : "r"(a0), "r"(a1), "r"(a2), "r"(a3), "r"(b0), "r"(b1));
}

// ---------------- layer-1 scatter: agg1[dst] += x[src], D=10 ----------------
__global__ void scatter1_kernel(const float* __restrict__ x,
                                const int* __restrict__ src,
                                const int* __restrict__ dst,
                                float* __restrict__ agg1, int E) {
    int e = blockIdx.x * blockDim.x + threadIdx.x;
    if (e >= E) return;
    int s = __ldg(&src[e]), d = __ldg(&dst[e]);
    const float2* xr = (const float2*)(x + (size_t)s * N_CLASS);
    float* ar = agg1 + (size_t)d * N_CLASS;
#pragma unroll
    for (int i = 0; i < 5; i++) {
        float2 v = __ldg(&xr[i]);
        red_add_v2(ar + 2 * i, v);
    }
}

// ---------------- GEMM1: z1 = (x + agg1) @ w11 + b11, K=10; accumulate BN stats ----------------
__global__ void gemm1_kernel(const float* __restrict__ x,
                             const float* __restrict__ agg1,
                             const float* __restrict__ w11,
                             const float* __restrict__ b11,
                             float* __restrict__ z1,
                             double* __restrict__ sumOut,
                             double* __restrict__ sqOut, int N) {
    __shared__ float ws[N_CLASS * HIDDEN];
    __shared__ float xs[8][N_CLASS];
    __shared__ float ssum[HIDDEN], ssq[HIDDEN];
    int tx = threadIdx.x, ty = threadIdx.y;
    int tid = ty * HIDDEN + tx;
    for (int i = tid; i < N_CLASS * HIDDEN; i += HIDDEN * 8) ws[i] = w11[i];
    if (tid < HIDDEN) { ssum[tid] = 0.f; ssq[tid] = 0.f; }
    int row = blockIdx.x * 8 + ty;
    if (tx < N_CLASS && row < N)
        xs[ty][tx] = x[(size_t)row * N_CLASS + tx] + agg1[(size_t)row * N_CLASS + tx];
    __syncthreads();
    if (row < N) {
        float z = __ldg(&b11[tx]);
#pragma unroll
        for (int k = 0; k < N_CLASS; k++) z += xs[ty][k] * ws[k * HIDDEN + tx];
        z1[(size_t)row * HIDDEN + tx] = z;
        atomicAdd(&ssum[tx], z);
        atomicAdd(&ssq[tx], z * z);
    }
    __syncthreads();
    if (tid < HIDDEN) {
        atomicAdd(&sumOut[tid], (double)ssum[tid]);
        atomicAdd(&sqOut[tid], (double)ssq[tid]);
    }
}

// ---------------- BN finalize ----------------
__global__ void bn_finalize(const double* __restrict__ sum,
                            const double* __restrict__ sq,
                            const float* __restrict__ g,
                            const float* __restrict__ t,
                            float* __restrict__ scale,
                            float* __restrict__ shift, double invN) {
    int j = threadIdx.x;
    double m = sum[j] * invN;
    double v = sq[j] * invN - m * m;
    if (v < 0.0) v = 0.0;
    double inv = (double)g[j] / sqrt(v + (double)BN_EPS);
    scale[j] = (float)inv;
    shift[j] = (float)((double)t[j] - m * inv);
}

// ---------------- main GEMM (TF32 tensor cores): Zout = act(A) @ W + bias + BN-stat epilogue ----
// MODE 0: act(z) = relu(scale*z + shift)
// MODE 1: act(z) = relu(scale*z + shift) + agg[row]
// CTA: 128 rows x 128 cols, 8 warps; warp tile 64x32 via m16n8k8 (4 m-tiles x 4 n-tiles).
// A streamed in two K-chunks of 64 (pitch APD=68) so smem ~101KB -> 2 CTAs/SM.
// tf32 m16n8k8 fragment maps (PTX ISA):
//   A: a0=(g,t) a1=(g+8,t) a2=(g,t+4) a3=(g+8,t+4)     (k local to chunk)
//   B: b0=(k=t,n=g) b1=(k=t+4,n=g)
//   D: d0=(g,2t) d1=(g,2t+1) d2=(g+8,2t) d3=(g+8,2t+1)
#define MTILE 128
#define KC 64
#define APD 68     // A chunk pitch (bank 4g+t -> conflict-free)
#define BPD 132    // B pitch      (bank 4t+g -> conflict-free)
template <int MODE>
__global__ __launch_bounds__(256, 2) void gemmB(
    const float* __restrict__ Ain, const float* __restrict__ agg,
    const float* __restrict__ W, const float* __restrict__ bias,
    const float* __restrict__ scale, const float* __restrict__ shift,
    float* __restrict__ Zout, double* __restrict__ sumOut,
    double* __restrict__ sqOut, int N) {
    extern __shared__ float smem[];
    float* Bs = smem;                        // [128][132] tf32
    float* As = Bs + HIDDEN * BPD;           // [128][68]  one 64-wide K chunk
    float* ssum = As + MTILE * APD;          // [128]
    float* ssq = ssum + HIDDEN;              // [128]
    __shared__ float sc[HIDDEN], sh[HIDDEN];

    int tid = threadIdx.x;
    int row0 = blockIdx.x * MTILE;
    if (tid < HIDDEN) {
        ssum[tid] = 0.f; ssq[tid] = 0.f;
        sc[tid] = scale[tid]; sh[tid] = shift[tid];
    }
    // load full B tile (128x128 weight) -> tf32
    for (int i = tid; i < HIDDEN * (HIDDEN / 4); i += 256) {
        int k = i / (HIDDEN / 4), c4 = (i % (HIDDEN / 4)) * 4;
        float4 w = *(const float4*)&W[k * HIDDEN + c4];
        w.x = to_tf32(w.x); w.y = to_tf32(w.y); w.z = to_tf32(w.z); w.w = to_tf32(w.w);
        *(float4*)&Bs[k * BPD + c4] = w;
    }

    int lane = tid & 31, wid = tid >> 5;
    int wm = wid & 1, wn = wid >> 1;          // warp tile: rows wm*64, cols wn*32
    int g = lane >> 2, t = lane & 3;          // groupID, thread-in-group

    float d[4][4][4];                          // [m-tile][n-tile][4 accum]
#pragma unroll
    for (int mt = 0; mt < 4; mt++)
#pragma unroll
        for (int nt = 0; nt < 4; nt++)
#pragma unroll
            for (int q = 0; q < 4; q++) d[mt][nt][q] = 0.f;

    for (int kc = 0; kc < HIDDEN; kc += KC) {
        __syncthreads();   // As reuse guard; first pass: orders Bs/sc/sh writes before reads
        // fill A chunk: 128 rows x 64 k  (BN+relu(+agg) transform, tf32 round)
        for (int i = tid; i < MTILE * (KC / 4); i += 256) {
            int r = i / (KC / 4), k4 = (i % (KC / 4)) * 4;
            int gk = kc + k4;
            int gr = row0 + r;
            float4 v = make_float4(0.f, 0.f, 0.f, 0.f);
            if (gr < N) {
                float4 z = *(const float4*)&Ain[(size_t)gr * HIDDEN + gk];
                v.x = fmaxf(0.f, sc[gk + 0] * z.x + sh[gk + 0]);
                v.y = fmaxf(0.f, sc[gk + 1] * z.y + sh[gk + 1]);
                v.z = fmaxf(0.f, sc[gk + 2] * z.z + sh[gk + 2]);
                v.w = fmaxf(0.f, sc[gk + 3] * z.w + sh[gk + 3]);
                if (MODE == 1) {
                    float4 a = *(const float4*)&agg[(size_t)gr * HIDDEN + gk];
                    v.x += a.x; v.y += a.y; v.z += a.z; v.w += a.w;
                }
                v.x = to_tf32(v.x); v.y = to_tf32(v.y); v.z = to_tf32(v.z); v.w = to_tf32(v.w);
            }
            *(float4*)&As[r * APD + k4] = v;
        }
        __syncthreads();

#pragma unroll
        for (int ks = 0; ks < KC / 8; ks++) {
            int k0 = ks * 8;          // k local to chunk (As)
            int kg = kc + k0;         // global k (Bs)
            uint32_t af[4][4];
#pragma unroll
            for (int mt = 0; mt < 4; mt++) {
                int m = wm * 64 + mt * 16;
                af[mt][0] = __float_as_uint(As[(m + g) * APD + k0 + t]);
                af[mt][1] = __float_as_uint(As[(m + g + 8) * APD + k0 + t]);
                af[mt][2] = __float_as_uint(As[(m + g) * APD + k0 + t + 4]);
                af[mt][3] = __float_as_uint(As[(m + g + 8) * APD + k0 + t + 4]);
            }
            uint32_t bf[4][2];
#pragma unroll
            for (int nt = 0; nt < 4; nt++) {
                int n = wn * 32 + nt * 8;
                bf[nt][0] = __float_as_uint(Bs[(kg + t) * BPD + n + g]);
                bf[nt][1] = __float_as_uint(Bs[(kg + t + 4) * BPD + n + g]);
            }
#pragma unroll
            for (int mt = 0; mt < 4; mt++)
#pragma unroll
                for (int nt = 0; nt < 4; nt++)
                    mma_tf32(d[mt][nt][0], d[mt][nt][1], d[mt][nt][2], d[mt][nt][3],
                             af[mt][0], af[mt][1], af[mt][2], af[mt][3],
                             bf[nt][0], bf[nt][1]);
        }
    }

    // epilogue: bias, store, column stats
    // d0 -> (g, 2t), d1 -> (g, 2t+1), d2 -> (g+8, 2t), d3 -> (g+8, 2t+1)
#pragma unroll
    for (int nt = 0; nt < 4; nt++) {
        int c = wn * 32 + nt * 8 + 2 * t;
        float b0 = __ldg(&bias[c]), b1 = __ldg(&bias[c + 1]);
        float ps0 = 0.f, ps1 = 0.f, pq0 = 0.f, pq1 = 0.f;
#pragma unroll
        for (int mt = 0; mt < 4; mt++) {
            int gr0 = row0 + wm * 64 + mt * 16 + g;
            int gr1 = gr0 + 8;
            if (gr0 < N) {
                float z0 = d[mt][nt][0] + b0;
                float z1 = d[mt][nt][1] + b1;
                ps0 += z0; pq0 += z0 * z0;
                ps1 += z1; pq1 += z1 * z1;
                *(float2*)&Zout[(size_t)gr0 * HIDDEN + c] = make_float2(z0, z1);
            }
            if (gr1 < N) {
                float z2 = d[mt][nt][2] + b0;
                float z3 = d[mt][nt][3] + b1;
                ps0 += z2; pq0 += z2 * z2;
                ps1 += z3; pq1 += z3 * z3;
                *(float2*)&Zout[(size_t)gr1 * HIDDEN + c] = make_float2(z2, z3);
            }
        }
        atomicAdd(&ssum[c], ps0);
        atomicAdd(&ssq[c], pq0);
        atomicAdd(&ssum[c + 1], ps1);
        atomicAdd(&ssq[c + 1], pq1);
    }
    __syncthreads();
    if (tid < HIDDEN) {
        atomicAdd(&sumOut[tid], (double)ssum[tid]);
        atomicAdd(&sqOut[tid], (double)ssq[tid]);
    }
}

// ---------------- layer-2 scatter: agg2[dst] += relu(bn(z2))[src], warp/edge, D=128 ----------
__global__ void scatter2_kernel(const float* __restrict__ z2,
                                const float* __restrict__ scale,
                                const float* __restrict__ shift,
                                const int* __restrict__ src,
                                const int* __restrict__ dst,
                                float* __restrict__ agg2, int E) {
    __shared__ float sc[HIDDEN], sh[HIDDEN];
    int tid = threadIdx.x;
    if (tid < HIDDEN) { sc[tid] = scale[tid]; sh[tid] = shift[tid]; }
    __syncthreads();
    int warp = tid >> 5, lane = tid & 31;
    int e = blockIdx.x * 8 + warp;
    if (e >= E) return;
    int s = __ldg(&src[e]);
    int d = __ldg(&dst[e]);
    int o = lane * 4;
    float4 z = *(const float4*)&z2[(size_t)s * HIDDEN + o];
    float4 v;
    v.x = fmaxf(0.f, sc[o + 0] * z.x + sh[o + 0]);
    v.y = fmaxf(0.f, sc[o + 1] * z.y + sh[o + 1]);
    v.z = fmaxf(0.f, sc[o + 2] * z.z + sh[o + 2]);
    v.w = fmaxf(0.f, sc[o + 3] * z.w + sh[o + 3]);
    red_add_v4(&agg2[(size_t)d * HIDDEN + o], v);
}

// ---------------- final: logits = relu(bn(z4)) @ wf + bf -> log_softmax, warp/row ----------
__global__ void final_kernel(const float* __restrict__ z4,
                             const float* __restrict__ scale,
                             const float* __restrict__ shift,
                             const float* __restrict__ wf,
                             const float* __restrict__ bf,
                             float* __restrict__ out, int N) {
    __shared__ float wfs[HIDDEN * N_CLASS];
    __shared__ float sc[HIDDEN], sh[HIDDEN];
    int tid = threadIdx.x;
    for (int i = tid; i < HIDDEN * N_CLASS; i += 256) wfs[i] = wf[i];
    if (tid < HIDDEN) { sc[tid] = scale[tid]; sh[tid] = shift[tid]; }
    __syncthreads();
    int warp = tid >> 5, lane = tid & 31;
    int n = blockIdx.x * 8 + warp;
    if (n >= N) return;
    int o = lane * 4;
    float4 z = *(const float4*)&z4[(size_t)n * HIDDEN + o];
    float y[4];
    y[0] = fmaxf(0.f, sc[o + 0] * z.x + sh[o + 0]);
    y[1] = fmaxf(0.f, sc[o + 1] * z.y + sh[o + 1]);
    y[2] = fmaxf(0.f, sc[o + 2] * z.z + sh[o + 2]);
    y[3] = fmaxf(0.f, sc[o + 3] * z.w + sh[o + 3]);
    float acc[N_CLASS];
#pragma unroll
    for (int j = 0; j < N_CLASS; j++) acc[j] = 0.f;
#pragma unroll
    for (int i = 0; i < 4; i++) {
        const float* wr = &wfs[(o + i) * N_CLASS];
#pragma unroll
        for (int j = 0; j < N_CLASS; j++) acc[j] = fmaf(y[i], wr[j], acc[j]);
    }
#pragma unroll
    for (int off = 16; off > 0; off >>= 1)
#pragma unroll
        for (int j = 0; j < N_CLASS; j++)
            acc[j] += __shfl_xor_sync(0xFFFFFFFFu, acc[j], off);
    if (lane == 0) {
        float l[N_CLASS];
        float m = -1e30f;
#pragma unroll
        for (int j = 0; j < N_CLASS; j++) {
            l[j] = acc[j] + __ldg(&bf[j]);
            m = fmaxf(m, l[j]);
        }
        float s = 0.f;
#pragma unroll
        for (int j = 0; j < N_CLASS; j++) s += __expf(l[j] - m);
        float lg = m + logf(s);
#pragma unroll
        for (int j = 0; j < N_CLASS; j++) out[(size_t)n * N_CLASS + j] = l[j] - lg;
    }
}

// ---------------- host launch ----------------
extern "C" void kernel_launch(void* const* d_in, const int* in_sizes, int n_in,
                              void* d_out, int out_size) {
    const float* x   = (const float*)d_in[0];
    const float* w11 = (const float*)d_in[2];
    const float* b11 = (const float*)d_in[3];
    const float* g11 = (const float*)d_in[4];
    const float* t11 = (const float*)d_in[5];
    const float* w12 = (const float*)d_in[6];
    const float* b12 = (const float*)d_in[7];
    const float* g12 = (const float*)d_in[8];
    const float* t12 = (const float*)d_in[9];
    const float* w21 = (const float*)d_in[10];
    const float* b21 = (const float*)d_in[11];
    const float* g21 = (const float*)d_in[12];
    const float* t21 = (const float*)d_in[13];
    const float* w22 = (const float*)d_in[14];
    const float* b22 = (const float*)d_in[15];
    const float* g22 = (const float*)d_in[16];
    const float* t22 = (const float*)d_in[17];
    const float* wf  = (const float*)d_in[18];
    const float* bf  = (const float*)d_in[19];
    const int*   ei  = (const int*)d_in[20];   // int32 on device (harness dtype set)

    int N = in_sizes[0] / N_CLASS;       // 100000
    int E = in_sizes[20] / 2;            // 1600000
    const int* src = ei;
    const int* dst = ei + E;

    float *agg1, *agg2, *buf1, *buf2, *scale, *shift;
    double *bnsum, *bnsq;
    cudaGetSymbolAddress((void**)&agg1, g_agg1);
    cudaGetSymbolAddress((void**)&agg2, g_agg2);
    cudaGetSymbolAddress((void**)&buf1, g_buf1);
    cudaGetSymbolAddress((void**)&buf2, g_buf2);
    cudaGetSymbolAddress((void**)&scale, g_scale);
    cudaGetSymbolAddress((void**)&shift, g_shift);
    cudaGetSymbolAddress((void**)&bnsum, g_bnsum);
    cudaGetSymbolAddress((void**)&bnsq, g_bnsq);

    const size_t SMEM_GEMM = (size_t)(HIDDEN * BPD + MTILE * APD + 2 * HIDDEN) * sizeof(float);
    cudaFuncSetAttribute(gemmB<0>, cudaFuncAttributeMaxDynamicSharedMemorySize, (int)SMEM_GEMM);
    cudaFuncSetAttribute(gemmB<1>, cudaFuncAttributeMaxDynamicSharedMemorySize, (int)SMEM_GEMM);

    cudaMemsetAsync(agg1, 0, (size_t)N * N_CLASS * sizeof(float), 0);
    cudaMemsetAsync(agg2, 0, (size_t)N * HIDDEN * sizeof(float), 0);
    cudaMemsetAsync(bnsum, 0, 4 * HIDDEN * sizeof(double), 0);
    cudaMemsetAsync(bnsq, 0, 4 * HIDDEN * sizeof(double), 0);

    double invN = 1.0 / (double)N;
    int gBlocks = (N + MTILE - 1) / MTILE;

    // layer 1
    scatter1_kernel<<<(E + 255) / 256, 256>>>(x, src, dst, agg1, E);
    gemm1_kernel<<<(N + 7) / 8, dim3(HIDDEN, 8)>>>(x, agg1, w11, b11, buf1,
                                                   bnsum + 0 * HIDDEN, bnsq + 0 * HIDDEN, N);
    bn_finalize<<<1, HIDDEN>>>(bnsum + 0 * HIDDEN, bnsq + 0 * HIDDEN, g11, t11,
                               scale + 0 * HIDDEN, shift + 0 * HIDDEN, invN);
    gemmB<0><<<gBlocks, 256, SMEM_GEMM>>>(buf1, nullptr, w12, b12,
                                          scale + 0 * HIDDEN, shift + 0 * HIDDEN,
                                          buf2, bnsum + 1 * HIDDEN, bnsq + 1 * HIDDEN, N);
    bn_finalize<<<1, HIDDEN>>>(bnsum + 1 * HIDDEN, bnsq + 1 * HIDDEN, g12, t12,
                               scale + 1 * HIDDEN, shift + 1 * HIDDEN, invN);

    // layer 2 (h_out1 = relu(bn1(z2)) recomputed on the fly; never materialized)
    scatter2_kernel<<<(E + 7) / 8, 256>>>(buf2, scale + 1 * HIDDEN, shift + 1 * HIDDEN,
                                          src, dst, agg2, E);
    gemmB<1><<<gBlocks, 256, SMEM_GEMM>>>(buf2, agg2, w21, b21,
                                          scale + 1 * HIDDEN, shift + 1 * HIDDEN,
                                          buf1, bnsum + 2 * HIDDEN, bnsq + 2 * HIDDEN, N);
    bn_finalize<<<1, HIDDEN>>>(bnsum + 2 * HIDDEN, bnsq + 2 * HIDDEN, g21, t21,
                               scale + 2 * HIDDEN, shift + 2 * HIDDEN, invN);
    gemmB<0><<<gBlocks, 256, SMEM_GEMM>>>(buf1, nullptr, w22, b22,
                                          scale + 2 * HIDDEN, shift + 2 * HIDDEN,
                                          buf2, bnsum + 3 * HIDDEN, bnsq + 3 * HIDDEN, N);
    bn_finalize<<<1, HIDDEN>>>(bnsum + 3 * HIDDEN, bnsq + 3 * HIDDEN, g22, t22,
                               scale + 3 * HIDDEN, shift + 3 * HIDDEN, invN);

    // readout
    final_kernel<<<(N + 7) / 8, 256>>>(buf2, scale + 3 * HIDDEN, shift + 3 * HIDDEN,
                                       wf, bf, (float*)d_out, N);
}